// round 1
// baseline (speedup 1.0000x reference)
#include <cuda_runtime.h>

#define N_NODES 50000
#define N_EDGES_MAX 800000
#define IN_FEAT 64
#define HID 32
#define GRIDP 4
#define NG 128

// ---------------- scratch (static device globals; no allocs allowed) --------
__device__ float g_h[N_NODES * HID];     // node features
__device__ float g_T[N_NODES * HID];     // per-node KAN-transformed messages
__device__ float g_acc[N_NODES * HID];   // scatter accumulation buffer
__device__ float g_sums[NG * HID];       // pooling sums
__device__ float g_cnt[NG];              // pooling counts
__device__ int   g_is64;                 // index dtype flag

// ---------------- helpers ---------------------------------------------------
__device__ __forceinline__ int ldidx(const void* p, long long i, int is64) {
    if (is64) return (int)__ldg((const long long*)p + i);
    return __ldg((const int*)p + i);
}

// Detect whether edge_index is int64 (little-endian high words all zero) or int32.
// Values are in [0, 50000): 32 consecutive random int32 src values all being
// zero is impossible, so this is unambiguous.
__global__ void k_detect(const void* ei) {
    const unsigned int* a = (const unsigned int*)ei;
    int is64 = 1;
    for (int i = 0; i < 32; i++)
        if (a[2 * i + 1] != 0u) is64 = 0;
    g_is64 = is64;
}

// ---------------- Fourier-KAN projection kernel -----------------------------
// y[n,o] = sum_{i,g} cos((g+1)*x[n,i]) * W0[o,i,g] + sin((g+1)*x[n,i]) * W1[o,i,g]
// One thread per node, 32 fp32 accumulators, W staged in shared (broadcast LDS),
// trig via one __sincosf + Chebyshev recurrence.
// FIRST=true : reads input x (IN=64), writes g_h.
// FIRST=false: reads g_h (IN=32), writes g_T, and zeroes g_acc row.
template <int IN, bool FIRST>
__global__ void k_kan(const float* __restrict__ xin, const float* __restrict__ W) {
    extern __shared__ float sw[];
    const int nW = 2 * HID * IN * GRIDP;
    for (int j = threadIdx.x; j < nW; j += blockDim.x) sw[j] = W[j];
    __syncthreads();

    int node = blockIdx.x * blockDim.x + threadIdx.x;
    if (node >= N_NODES) return;

    const float* in = FIRST ? (xin + (size_t)node * IN) : (g_h + node * IN);
    const float4* w0 = (const float4*)sw;               // [o*IN + i] -> (g0..g3)
    const float4* w1 = (const float4*)sw + HID * IN;

    float acc[HID];
#pragma unroll
    for (int o = 0; o < HID; o++) acc[o] = 0.f;

#pragma unroll 1
    for (int i = 0; i < IN; i++) {
        float xv = in[i];
        float s1, c1;
        __sincosf(xv, &s1, &c1);
        float t = 2.f * c1;
        float c2 = fmaf(t, c1, -1.f);
        float s2 = t * s1;
        float c3 = fmaf(t, c2, -c1);
        float s3 = fmaf(t, s2, -s1);
        float c4 = fmaf(t, c3, -c2);
        float s4 = fmaf(t, s3, -s2);
#pragma unroll
        for (int o = 0; o < HID; o++) {
            float4 a0 = w0[o * IN + i];
            float4 a1 = w1[o * IN + i];
            float v = c1 * a0.x;
            v = fmaf(c2, a0.y, v);
            v = fmaf(c3, a0.z, v);
            v = fmaf(c4, a0.w, v);
            float u = s1 * a1.x;
            u = fmaf(s2, a1.y, u);
            u = fmaf(s3, a1.z, u);
            u = fmaf(s4, a1.w, u);
            acc[o] += v + u;
        }
    }

    float* outp = FIRST ? (g_h + node * HID) : (g_T + node * HID);
    float4* o4 = (float4*)outp;
#pragma unroll
    for (int j = 0; j < HID / 4; j++)
        o4[j] = make_float4(acc[4 * j], acc[4 * j + 1], acc[4 * j + 2], acc[4 * j + 3]);

    if (!FIRST) {  // zero the scatter buffer for this node
        float4 z = make_float4(0.f, 0.f, 0.f, 0.f);
        float4* a4 = (float4*)(g_acc + node * HID);
#pragma unroll
        for (int j = 0; j < HID / 4; j++) a4[j] = z;
    }
}

// ---------------- edge scatter: acc[dst] += T[src] --------------------------
// 8 threads per edge, each moving one float4 (vector reduction atomics).
__global__ void k_scatter(const void* __restrict__ ei, int E) {
    long long gid = (long long)blockIdx.x * blockDim.x + threadIdx.x;
    int e = (int)(gid >> 3);
    int q = (int)(gid & 7);
    if (e >= E) return;
    int is64 = g_is64;
    int src = ldidx(ei, e, is64);
    int dst = ldidx(ei, (long long)E + e, is64);
    float4 v = __ldg((const float4*)g_T + src * (HID / 4) + q);
    float* p = g_acc + dst * HID + q * 4;
    asm volatile("red.global.add.v4.f32 [%0], {%1, %2, %3, %4};"
                 :: "l"(p), "f"(v.x), "f"(v.y), "f"(v.z), "f"(v.w)
                 : "memory");
}

// ---------------- h = leaky_relu(acc + h) -----------------------------------
__device__ __forceinline__ float lrelu(float v) { return v > 0.f ? v : 0.01f * v; }

__global__ void k_relu() {
    int j = blockIdx.x * blockDim.x + threadIdx.x;
    if (j >= N_NODES * HID / 4) return;
    float4 m = ((const float4*)g_acc)[j];
    float4 h = ((const float4*)g_h)[j];
    float4 r;
    r.x = lrelu(m.x + h.x);
    r.y = lrelu(m.y + h.y);
    r.z = lrelu(m.z + h.z);
    r.w = lrelu(m.w + h.w);
    ((float4*)g_h)[j] = r;
}

// ---------------- pooling ---------------------------------------------------
__global__ void k_zero_pool() {
    int j = blockIdx.x * blockDim.x + threadIdx.x;
    if (j < NG * HID) g_sums[j] = 0.f;
    if (j < NG) g_cnt[j] = 0.f;
}

// one warp per node: lane c adds h[n,c] into sums[batch[n], c]
__global__ void k_pool(const void* __restrict__ batch) {
    int warp = (blockIdx.x * blockDim.x + threadIdx.x) >> 5;
    int lane = threadIdx.x & 31;
    if (warp >= N_NODES) return;
    int b = ldidx(batch, warp, g_is64);
    float v = g_h[warp * HID + lane];
    atomicAdd(&g_sums[b * HID + lane], v);
    if (lane == 0) atomicAdd(&g_cnt[b], 1.f);
}

// ---------------- readout: sigmoid(KAN_linear(mean_pool)) -------------------
__global__ void k_readout(const float* __restrict__ Wout,
                          const float* __restrict__ bout,
                          float* __restrict__ out) {
    int g = threadIdx.x;
    if (g >= NG) return;
    float cnt = fmaxf(g_cnt[g], 1.f);
    float inv = 1.f / cnt;
    float acc = 0.f;
#pragma unroll
    for (int c = 0; c < HID; c++) {
        float y = g_sums[g * HID + c] * inv;
        float s, co;
        __sincosf(y, &s, &co);
        acc = fmaf(co, Wout[c], acc);
        acc = fmaf(s, Wout[HID + c], acc);
    }
    acc += bout[0];
    out[g] = 1.f / (1.f + __expf(-acc));
}

// ---------------- launch ----------------------------------------------------
extern "C" void kernel_launch(void* const* d_in, const int* in_sizes, int n_in,
                              void* d_out, int out_size) {
    const float* x      = (const float*)d_in[0];
    const void*  ei     = d_in[1];
    const void*  batch  = d_in[2];
    const float* W_in   = (const float*)d_in[3];
    const float* W_conv = (const float*)d_in[4];
    const float* W_out  = (const float*)d_in[5];
    const float* b_out  = (const float*)d_in[6];
    float* out = (float*)d_out;

    int E = in_sizes[1] / 2;  // element count is dtype-independent

    // 64 KB dynamic smem for the input-layer weight stage (over the 48 KB default)
    cudaFuncSetAttribute(k_kan<IN_FEAT, true>,
                         cudaFuncAttributeMaxDynamicSharedMemorySize, 65536);

    k_detect<<<1, 1>>>(ei);

    int nb = (N_NODES + 127) / 128;
    k_kan<IN_FEAT, true><<<nb, 128, 2 * HID * IN_FEAT * GRIDP * sizeof(float)>>>(x, W_in);

    for (int l = 0; l < 2; l++) {
        const float* Wl = W_conv + (size_t)l * 2 * HID * HID * GRIDP;
        k_kan<HID, false><<<nb, 128, 2 * HID * HID * GRIDP * sizeof(float)>>>(nullptr, Wl);

        long long tthreads = (long long)E * 8;
        int sb = (int)((tthreads + 255) / 256);
        k_scatter<<<sb, 256>>>(ei, E);

        k_relu<<<(N_NODES * HID / 4 + 255) / 256, 256>>>();
    }

    k_zero_pool<<<(NG * HID + NG + 255) / 256, 256>>>();
    k_pool<<<(N_NODES + 7) / 8, 256>>>(batch);
    k_readout<<<1, 128>>>(W_out, b_out, out);
}

// round 2
// speedup vs baseline: 1.3246x; 1.3246x over previous
#include <cuda_runtime.h>

typedef unsigned long long ull;

#define N_NODES 50000
#define IN_FEAT 64
#define HID 32
#define GRIDP 4
#define NG 128

// ---------------- scratch (static device globals; no allocs allowed) --------
__device__ float g_h[N_NODES * HID];
__device__ float g_T[N_NODES * HID];
__device__ float g_acc[N_NODES * HID];
__device__ float g_sums[NG * HID];
__device__ float g_cnt[NG];
__device__ int   g_is64;

// ---------------- helpers ---------------------------------------------------
__device__ __forceinline__ int ldidx(const void* p, long long i, int is64) {
    if (is64) return (int)__ldg((const long long*)p + i);
    return __ldg((const int*)p + i);
}

__device__ __forceinline__ ull pk2(float a, float b) {
    ull r; asm("mov.b64 %0, {%1,%2};" : "=l"(r) : "f"(a), "f"(b)); return r;
}
// Packed dual-fp32 FMA (Blackwell f32x2 path: 2 FMAs per issue slot, full fp32)
__device__ __forceinline__ ull ffma2(ull a, ull b, ull c) {
    ull d; asm("fma.rn.f32x2 %0, %1, %2, %3;" : "=l"(d) : "l"(a), "l"(b), "l"(c));
    return d;
}

__device__ __forceinline__ float lrelu(float v) { return v > 0.f ? v : 0.01f * v; }

// ---------------- init: zero pool buffers + detect index dtype --------------
__global__ void k_init(const void* ei) {
    int j = blockIdx.x * blockDim.x + threadIdx.x;
    if (j < NG * HID) g_sums[j] = 0.f;
    if (j < NG) g_cnt[j] = 0.f;
    if (j == 0) {
        const unsigned* a = (const unsigned*)ei;
        int is64 = 1;
        for (int i = 0; i < 32; i++)
            if (a[2 * i + 1] != 0u) is64 = 0;
        g_is64 = is64;
    }
}

// ---------------- Fourier-KAN projection (FFMA2 formulation) ----------------
// y[n,o] = sum_{i,g} cos((g+1)x[n,i])*W0[o,i,g] + sin((g+1)x[n,i])*W1[o,i,g]
// Outputs paired (o even/odd) into f32x2 lanes; weights repacked in shared as
// interleaved float2 so each (i, o-pair) is 4 LDS.128 + 8 FFMA2.
// MODE 0: in = x,               out = g_h
// MODE 1: in = g_h,             out = g_T, zero g_acc
// MODE 2: in = lrelu(acc + h)   (writes h back), out = g_T, zero g_acc
template <int IN, int MODE>
__global__ __launch_bounds__(128) void k_kan(const float* __restrict__ xin,
                                             const float* __restrict__ W) {
    extern __shared__ float sw[];
    const int nW = 2 * HID * IN * GRIDP;
    // repack W[s][o][i][g] -> sw[((s*IN+i)*16 + o/2)*8 + g*2 + (o&1)]
    for (int j = threadIdx.x; j < nW; j += blockDim.x) {
        int g = j & 3;
        int rem = j >> 2;
        int i = rem % IN;
        int o = (rem / IN) & (HID - 1);
        int s = rem / (IN * HID);
        sw[((s * IN + i) * 16 + (o >> 1)) * 8 + g * 2 + (o & 1)] = W[j];
    }
    __syncthreads();

    int node = blockIdx.x * blockDim.x + threadIdx.x;
    if (node >= N_NODES) return;

    const ull* swu = (const ull*)sw;
    const int sinoff = IN * 64;  // ull units per s-block

    ull acc[16];
#pragma unroll
    for (int t = 0; t < 16; t++) acc[t] = 0ull;

    const float4* xp = (MODE == 0) ? (const float4*)(xin + (size_t)node * IN)
                                   : (const float4*)(g_h + node * HID);
    const float4* ap = (const float4*)(g_acc + node * HID);
    float4* hp = (float4*)(g_h + node * HID);

#pragma unroll 1
    for (int ib = 0; ib < IN / 4; ib++) {
        float4 xv4;
        if (MODE == 2) {
            float4 m = ap[ib];
            float4 h = hp[ib];
            xv4.x = lrelu(m.x + h.x); xv4.y = lrelu(m.y + h.y);
            xv4.z = lrelu(m.z + h.z); xv4.w = lrelu(m.w + h.w);
            hp[ib] = xv4;  // h_{l+1} written back for the next residual
        } else {
            xv4 = __ldg(xp + ib);
        }
#pragma unroll
        for (int u = 0; u < 4; u++) {
            int i = ib * 4 + u;
            float xv = (&xv4.x)[u];
            float s1, c1;
            __sincosf(xv, &s1, &c1);
            float t2 = 2.f * c1;
            float c2 = fmaf(t2, c1, -1.f), s2 = t2 * s1;
            float c3 = fmaf(t2, c2, -c1),  s3 = fmaf(t2, s2, -s1);
            float c4 = fmaf(t2, c3, -c2),  s4 = fmaf(t2, s3, -s2);
            ull cc1 = pk2(c1, c1), cc2 = pk2(c2, c2), cc3 = pk2(c3, c3), cc4 = pk2(c4, c4);
            ull ss1 = pk2(s1, s1), ss2 = pk2(s2, s2), ss3 = pk2(s3, s3), ss4 = pk2(s4, s4);
            const ulonglong2* pc = (const ulonglong2*)(swu + (size_t)i * 64);
            const ulonglong2* ps = (const ulonglong2*)(swu + sinoff + (size_t)i * 64);
#pragma unroll
            for (int op = 0; op < 16; op++) {
                ulonglong2 w01 = pc[op * 2], w23 = pc[op * 2 + 1];
                ull a = acc[op];
                a = ffma2(cc1, w01.x, a);
                a = ffma2(cc2, w01.y, a);
                a = ffma2(cc3, w23.x, a);
                a = ffma2(cc4, w23.y, a);
                ulonglong2 v01 = ps[op * 2], v23 = ps[op * 2 + 1];
                a = ffma2(ss1, v01.x, a);
                a = ffma2(ss2, v01.y, a);
                a = ffma2(ss3, v23.x, a);
                a = ffma2(ss4, v23.y, a);
                acc[op] = a;
            }
        }
    }

    ull* po = (ull*)(((MODE == 0) ? g_h : g_T) + node * HID);
#pragma unroll
    for (int op = 0; op < 16; op++) po[op] = acc[op];

    if (MODE != 0) {  // zero the scatter buffer row for the upcoming scatter
        float4 z = make_float4(0.f, 0.f, 0.f, 0.f);
        float4* az = (float4*)(g_acc + node * HID);
#pragma unroll
        for (int j = 0; j < 8; j++) az[j] = z;
    }
}

// ---------------- edge scatter: acc[dst] += T[src] --------------------------
// 8 lanes per edge, one float4 each; indices loaded once per edge (lane q==0)
// and broadcast via shuffle to halve LSU pressure.
__global__ void k_scatter(const void* __restrict__ ei, int E) {
    long long gid = (long long)blockIdx.x * blockDim.x + threadIdx.x;
    int e = (int)(gid >> 3);
    int q = (int)(gid & 7);
    bool valid = e < E;
    int is64 = g_is64;
    int s0 = 0, d0 = 0;
    if (valid && q == 0) {
        s0 = ldidx(ei, e, is64);
        d0 = ldidx(ei, (long long)E + e, is64);
    }
    int lead = threadIdx.x & ~7;
    int src = __shfl_sync(0xffffffffu, s0, lead);
    int dst = __shfl_sync(0xffffffffu, d0, lead);
    if (!valid) return;
    float4 v = __ldg((const float4*)g_T + src * (HID / 4) + q);
    float* p = g_acc + dst * HID + q * 4;
    asm volatile("red.global.add.v4.f32 [%0], {%1, %2, %3, %4};"
                 :: "l"(p), "f"(v.x), "f"(v.y), "f"(v.z), "f"(v.w)
                 : "memory");
}

// ---------------- pooling (fused final leaky-relu + residual) ---------------
__global__ void k_pool(const void* __restrict__ batch) {
    int warp = (blockIdx.x * blockDim.x + threadIdx.x) >> 5;
    int lane = threadIdx.x & 31;
    if (warp >= N_NODES) return;
    int b = ldidx(batch, warp, g_is64);
    float m = g_acc[warp * HID + lane];
    float h = g_h[warp * HID + lane];
    float v = lrelu(m + h);
    atomicAdd(&g_sums[b * HID + lane], v);
    if (lane == 0) atomicAdd(&g_cnt[b], 1.f);
}

// ---------------- readout: sigmoid(KAN_linear(mean_pool)) -------------------
__global__ void k_readout(const float* __restrict__ Wout,
                          const float* __restrict__ bout,
                          float* __restrict__ out) {
    int g = threadIdx.x;
    if (g >= NG) return;
    float cnt = fmaxf(g_cnt[g], 1.f);
    float inv = 1.f / cnt;
    float acc = 0.f;
#pragma unroll
    for (int c = 0; c < HID; c++) {
        float y = g_sums[g * HID + c] * inv;
        float s, co;
        __sincosf(y, &s, &co);
        acc = fmaf(co, Wout[c], acc);
        acc = fmaf(s, Wout[HID + c], acc);
    }
    acc += bout[0];
    out[g] = 1.f / (1.f + __expf(-acc));
}

// ---------------- launch ----------------------------------------------------
extern "C" void kernel_launch(void* const* d_in, const int* in_sizes, int n_in,
                              void* d_out, int out_size) {
    const float* x      = (const float*)d_in[0];
    const void*  ei     = d_in[1];
    const void*  batch  = d_in[2];
    const float* W_in   = (const float*)d_in[3];
    const float* W_conv = (const float*)d_in[4];
    const float* W_out  = (const float*)d_in[5];
    const float* b_out  = (const float*)d_in[6];
    float* out = (float*)d_out;

    int E = in_sizes[1] / 2;

    cudaFuncSetAttribute(k_kan<IN_FEAT, 0>,
                         cudaFuncAttributeMaxDynamicSharedMemorySize, 65536);

    k_init<<<16, 256>>>(ei);

    int nb = (N_NODES + 127) / 128;
    k_kan<IN_FEAT, 0><<<nb, 128, 2 * HID * IN_FEAT * GRIDP * sizeof(float)>>>(x, W_in);

    const int convW = 2 * HID * HID * GRIDP;

    // layer 0: transform h -> T, scatter
    k_kan<HID, 1><<<nb, 128, convW * sizeof(float)>>>(nullptr, W_conv);
    {
        long long tthreads = (long long)E * 8;
        int sb = (int)((tthreads + 255) / 256);
        k_scatter<<<sb, 256>>>(ei, E);
    }

    // layer 1: fused lrelu(acc+h) -> transform -> T, scatter
    k_kan<HID, 2><<<nb, 128, convW * sizeof(float)>>>(nullptr, W_conv + convW);
    {
        long long tthreads = (long long)E * 8;
        int sb = (int)((tthreads + 255) / 256);
        k_scatter<<<sb, 256>>>(ei, E);
    }

    k_pool<<<(N_NODES + 7) / 8, 256>>>(batch);
    k_readout<<<1, 128>>>(W_out, b_out, out);
}